// round 1
// baseline (speedup 1.0000x reference)
#include <cuda_runtime.h>

// Problem dimensions (fixed by the dataset).
#define L_DIM 16384
#define P_DIM 512
#define NCHUNK 128
#define CLEN (L_DIM / NCHUNK)   // 128

// ---------------- scratch (device globals: no allocation allowed) ----------
__device__ float g_lbr[P_DIM], g_lbi[P_DIM];   // Lambda_bar (fp32, matches jax path)
__device__ float g_bcr[P_DIM], g_bci[P_DIM];   // B_coef
__device__ double g_Ar[P_DIM], g_Ai[P_DIM];    // Lambda_bar^CLEN (double, near-exact)
__device__ float g_cfr[NCHUNK * P_DIM], g_cfi[NCHUNK * P_DIM];  // chunk-final states
__device__ float g_cir[NCHUNK * P_DIM], g_cii[NCHUNK * P_DIM];  // chunk carry-ins
__device__ float g_xr[(size_t)L_DIM * P_DIM];  // scan output, real plane
__device__ float g_xi[(size_t)L_DIM * P_DIM];  // scan output, imag plane

// ---------------- per-channel constants ------------------------------------
__global__ void setup_kernel(const float* __restrict__ Lambda,
                             const float* __restrict__ log_step) {
    int p = blockIdx.x * blockDim.x + threadIdx.x;
    if (p >= P_DIM) return;
    // Follow the reference's fp32 arithmetic as closely as possible.
    float lre = -expf(Lambda[2 * p + 0]);   // Re(Lambda_tilde) < 0
    float lim =  Lambda[2 * p + 1];         // Im(Lambda_tilde)
    float s   =  expf(log_step[p]);
    float zr = lre * s;
    float zi = lim * s;
    float er = expf(zr);
    float lbr = er * cosf(zi);
    float lbi = er * sinf(zi);
    g_lbr[p] = lbr;
    g_lbi[p] = lbi;
    // B_coef = (Lambda_bar - 1) / Lambda_tilde  (complex division)
    float den = lre * lre + lim * lim;
    float nr = lbr - 1.0f, ni = lbi;
    g_bcr[p] = (nr * lre + ni * lim) / den;
    g_bci[p] = (ni * lre - nr * lim) / den;
    // Chunk multiplier lam^CLEN: exact-ish in double via repeated squaring of
    // the fp32-rounded lam (the fp32 lam value IS the reference's operand).
    double ar = 1.0, ai = 0.0;
    double br = (double)lbr, bi = (double)lbi;
    int e = CLEN;
    while (e) {
        if (e & 1) {
            double t = ar * br - ai * bi;
            ai = ar * bi + ai * br;
            ar = t;
        }
        double t2 = br * br - bi * bi;
        bi = 2.0 * br * bi;
        br = t2;
        e >>= 1;
    }
    g_Ar[p] = ar;
    g_Ai[p] = ai;
}

// ---------------- pass 1: local scans (zero init), record chunk finals -----
__global__ void local_scan_kernel(const float* __restrict__ u) {
    int p = threadIdx.x;           // channel (512 threads -> coalesced u reads)
    int c = blockIdx.x;            // chunk
    float lr = g_lbr[p], li = g_lbi[p];
    float br = g_bcr[p], bi = g_bci[p];
    float xr = 0.0f, xi = 0.0f;
    const float* up = u + (size_t)(c * CLEN) * P_DIM + p;
#pragma unroll 4
    for (int i = 0; i < CLEN; i++) {
        float uv = up[(size_t)i * P_DIM];
        float nr = fmaf(lr, xr, fmaf(-li, xi, br * uv));
        float ni = fmaf(lr, xi, fmaf( li, xr, bi * uv));
        xr = nr; xi = ni;
    }
    g_cfr[c * P_DIM + p] = xr;
    g_cfi[c * P_DIM + p] = xi;
}

// ---------------- pass 2: carry sweep across chunks (double) ---------------
__global__ void carry_kernel() {
    int p = threadIdx.x;
    double ar = g_Ar[p], ai = g_Ai[p];
    double cr = 0.0, ci = 0.0;
    for (int c = 0; c < NCHUNK; c++) {
        g_cir[c * P_DIM + p] = (float)cr;   // exclusive carry-in
        g_cii[c * P_DIM + p] = (float)ci;
        double fr = (double)g_cfr[c * P_DIM + p];
        double fi = (double)g_cfi[c * P_DIM + p];
        double nr = ar * cr - ai * ci + fr;
        double ni = ar * ci + ai * cr + fi;
        cr = nr; ci = ni;
    }
}

// ---------------- pass 3: final scans with carry-in, write x planes --------
__global__ void final_scan_kernel(const float* __restrict__ u) {
    int p = threadIdx.x;
    int c = blockIdx.x;
    float lr = g_lbr[p], li = g_lbi[p];
    float br = g_bcr[p], bi = g_bci[p];
    float xr = g_cir[c * P_DIM + p];
    float xi = g_cii[c * P_DIM + p];
    const size_t base = (size_t)(c * CLEN) * P_DIM + p;
    const float* up = u + base;
    float* oxr = g_xr + base;
    float* oxi = g_xi + base;
#pragma unroll 4
    for (int i = 0; i < CLEN; i++) {
        float uv = up[(size_t)i * P_DIM];
        float nr = fmaf(lr, xr, fmaf(-li, xi, br * uv));
        float ni = fmaf(lr, xi, fmaf( li, xr, bi * uv));
        xr = nr; xi = ni;
        oxr[(size_t)i * P_DIM] = xr;
        oxi[(size_t)i * P_DIM] = xi;
    }
}

// ---------------- GEMM + spike: out = (Xr Vr^T - Xi Vi^T) > 1 --------------
#define BM 128
#define BN 128
#define BK 16
#define SPAD 4

__global__ __launch_bounds__(256, 2)
void gemm_spike_kernel(const float* __restrict__ Vr,
                       const float* __restrict__ Vi,
                       float* __restrict__ out) {
    __shared__ float sAr[BK][BM + SPAD];
    __shared__ float sAi[BK][BM + SPAD];
    __shared__ float sBr[BK][BN + SPAD];
    __shared__ float sBi[BK][BN + SPAD];

    const float* __restrict__ Xr = g_xr;
    const float* __restrict__ Xi = g_xi;

    const int tid = threadIdx.x;
    const int bm = blockIdx.y * BM;   // L tile
    const int bn = blockIdx.x * BN;   // output-channel tile

    const int lrow = tid >> 2;          // 0..63 (loads rows lrow, lrow+64)
    const int lcol = (tid & 3) << 2;    // 0,4,8,12

    const int ty = tid >> 4;            // 0..15
    const int tx = tid & 15;            // 0..15

    float acc[8][8];
#pragma unroll
    for (int i = 0; i < 8; i++)
#pragma unroll
        for (int j = 0; j < 8; j++) acc[i][j] = 0.0f;

    for (int kk = 0; kk < P_DIM; kk += BK) {
#pragma unroll
        for (int rr = 0; rr < 2; rr++) {
            int r = lrow + rr * 64;
            float4 a4r = *(const float4*)(Xr + (size_t)(bm + r) * P_DIM + kk + lcol);
            float4 a4i = *(const float4*)(Xi + (size_t)(bm + r) * P_DIM + kk + lcol);
            sAr[lcol + 0][r] = a4r.x; sAr[lcol + 1][r] = a4r.y;
            sAr[lcol + 2][r] = a4r.z; sAr[lcol + 3][r] = a4r.w;
            sAi[lcol + 0][r] = a4i.x; sAi[lcol + 1][r] = a4i.y;
            sAi[lcol + 2][r] = a4i.z; sAi[lcol + 3][r] = a4i.w;
            float4 b4r = *(const float4*)(Vr + (size_t)(bn + r) * P_DIM + kk + lcol);
            float4 b4i = *(const float4*)(Vi + (size_t)(bn + r) * P_DIM + kk + lcol);
            sBr[lcol + 0][r] = b4r.x; sBr[lcol + 1][r] = b4r.y;
            sBr[lcol + 2][r] = b4r.z; sBr[lcol + 3][r] = b4r.w;
            sBi[lcol + 0][r] = b4i.x; sBi[lcol + 1][r] = b4i.y;
            sBi[lcol + 2][r] = b4i.z; sBi[lcol + 3][r] = b4i.w;
        }
        __syncthreads();

#pragma unroll
        for (int k = 0; k < BK; k++) {
            float ar[8], ai[8], br[8], bi[8];
#pragma unroll
            for (int i = 0; i < 8; i += 4) {
                float4 v;
                v = *(const float4*)&sAr[k][ty * 8 + i];
                ar[i] = v.x; ar[i + 1] = v.y; ar[i + 2] = v.z; ar[i + 3] = v.w;
                v = *(const float4*)&sAi[k][ty * 8 + i];
                ai[i] = v.x; ai[i + 1] = v.y; ai[i + 2] = v.z; ai[i + 3] = v.w;
                v = *(const float4*)&sBr[k][tx * 8 + i];
                br[i] = v.x; br[i + 1] = v.y; br[i + 2] = v.z; br[i + 3] = v.w;
                v = *(const float4*)&sBi[k][tx * 8 + i];
                bi[i] = v.x; bi[i + 1] = v.y; bi[i + 2] = v.z; bi[i + 3] = v.w;
            }
#pragma unroll
            for (int i = 0; i < 8; i++)
#pragma unroll
                for (int j = 0; j < 8; j++) {
                    acc[i][j] = fmaf(ar[i], br[j], acc[i][j]);
                    acc[i][j] = fmaf(-ai[i], bi[j], acc[i][j]);
                }
        }
        __syncthreads();
    }

    // Epilogue: threshold and store (vectorized).
#pragma unroll
    for (int i = 0; i < 8; i++) {
        float* o = out + (size_t)(bm + ty * 8 + i) * P_DIM + bn + tx * 8;
#pragma unroll
        for (int j = 0; j < 8; j += 4) {
            float4 v;
            v.x = acc[i][j + 0] > 1.0f ? 1.0f : 0.0f;
            v.y = acc[i][j + 1] > 1.0f ? 1.0f : 0.0f;
            v.z = acc[i][j + 2] > 1.0f ? 1.0f : 0.0f;
            v.w = acc[i][j + 3] > 1.0f ? 1.0f : 0.0f;
            *(float4*)(o + j) = v;
        }
    }
}

// ---------------- launch -----------------------------------------------------
extern "C" void kernel_launch(void* const* d_in, const int* in_sizes, int n_in,
                              void* d_out, int out_size) {
    const float* u        = (const float*)d_in[0];   // (L, P)
    const float* Lambda   = (const float*)d_in[1];   // (P, 2)
    const float* log_step = (const float*)d_in[2];   // (P, 1)
    const float* V_re     = (const float*)d_in[3];   // (P, P)
    const float* V_im     = (const float*)d_in[4];   // (P, P)
    float* out            = (float*)d_out;           // (L, P) float32 spikes

    (void)in_sizes; (void)n_in; (void)out_size;

    setup_kernel<<<1, P_DIM>>>(Lambda, log_step);
    local_scan_kernel<<<NCHUNK, P_DIM>>>(u);
    carry_kernel<<<1, P_DIM>>>();
    final_scan_kernel<<<NCHUNK, P_DIM>>>(u);

    dim3 grid(P_DIM / BN, L_DIM / BM);
    gemm_spike_kernel<<<grid, 256>>>(V_re, V_im, out);
}

// round 3
// speedup vs baseline: 1.5297x; 1.5297x over previous
#include <cuda_runtime.h>
#include <cuda_fp16.h>
#include <cstdint>

// ---------------------------------------------------------------- dims
#define L_DIM 16384
#define P_DIM 512
#define NCHUNK 128
#define CLEN (L_DIM / NCHUNK)        // 128
#define KTOT 1024                    // complex concat: [Xr | Xi]

// ---------------------------------------------------------------- scratch
__device__ float g_lbr[P_DIM], g_lbi[P_DIM];
__device__ float g_bcr[P_DIM], g_bci[P_DIM];
__device__ double g_Ar[P_DIM], g_Ai[P_DIM];
__device__ float g_cfr[NCHUNK * P_DIM], g_cfi[NCHUNK * P_DIM];
__device__ float g_cir[NCHUNK * P_DIM], g_cii[NCHUNK * P_DIM];
// A = [Xr | Xi] as fp16 Dekker split planes, row-major [L][1024]
__device__ __half g_ah[(size_t)L_DIM * KTOT];
__device__ __half g_al[(size_t)L_DIM * KTOT];
// B = [Vr | -Vi] split planes, row-major [512][1024] (row = output channel)
__device__ __half g_bh[P_DIM * KTOT];
__device__ __half g_bl[P_DIM * KTOT];

// ---------------------------------------------------------------- helpers
__device__ __forceinline__ uint32_t smem_u32(const void* p) {
    uint32_t a;
    asm("{ .reg .u64 t; cvta.to.shared.u64 t, %1; cvt.u32.u64 %0, t; }" : "=r"(a) : "l"(p));
    return a;
}
__device__ __forceinline__ void split_h(float x, __half& h, __half& l) {
    h = __float2half_rn(x);
    float r = x - __half2float(h);
    l = __float2half_rn(r);
}
__device__ __forceinline__ void cp16(uint32_t dst, const void* src) {
    asm volatile("cp.async.cg.shared.global [%0], [%1], 16;" :: "r"(dst), "l"(src));
}
__device__ __forceinline__ void ldsm4(uint32_t* r, uint32_t addr) {
    asm volatile("ldmatrix.sync.aligned.m8n8.x4.shared.b16 {%0,%1,%2,%3}, [%4];"
                 : "=r"(r[0]), "=r"(r[1]), "=r"(r[2]), "=r"(r[3]) : "r"(addr));
}
#define MMA16816(c, a, b)                                                        \
    asm volatile("mma.sync.aligned.m16n8k16.row.col.f32.f16.f16.f32 "            \
                 "{%0,%1,%2,%3}, {%4,%5,%6,%7}, {%8,%9}, {%0,%1,%2,%3};"         \
                 : "+f"((c)[0]), "+f"((c)[1]), "+f"((c)[2]), "+f"((c)[3])        \
                 : "r"((a)[0]), "r"((a)[1]), "r"((a)[2]), "r"((a)[3]),           \
                   "r"((b)[0]), "r"((b)[1]))

// ---------------------------------------------------------------- setup
__global__ void setup_kernel(const float* __restrict__ Lambda,
                             const float* __restrict__ log_step) {
    int p = blockIdx.x * blockDim.x + threadIdx.x;
    if (p >= P_DIM) return;
    float lre = -expf(Lambda[2 * p + 0]);
    float lim =  Lambda[2 * p + 1];
    float s   =  expf(log_step[p]);
    float er  =  expf(lre * s);
    float lbr = er * cosf(lim * s);
    float lbi = er * sinf(lim * s);
    g_lbr[p] = lbr; g_lbi[p] = lbi;
    float den = lre * lre + lim * lim;
    float nr = lbr - 1.0f, ni = lbi;
    g_bcr[p] = (nr * lre + ni * lim) / den;
    g_bci[p] = (ni * lre - nr * lim) / den;
    double ar = 1.0, ai = 0.0, br = (double)lbr, bi = (double)lbi;
    int e = CLEN;
    while (e) {
        if (e & 1) { double t = ar * br - ai * bi; ai = ar * bi + ai * br; ar = t; }
        double t2 = br * br - bi * bi; bi = 2.0 * br * bi; br = t2;
        e >>= 1;
    }
    g_Ar[p] = ar; g_Ai[p] = ai;
}

// fp16 split of B = [Vr | -Vi]
__global__ void bprep_kernel(const float* __restrict__ Vr,
                             const float* __restrict__ Vi) {
    int n = blockIdx.x;
    for (int k = threadIdx.x; k < KTOT; k += blockDim.x) {
        float v = (k < P_DIM) ? Vr[n * P_DIM + k] : -Vi[n * P_DIM + (k - P_DIM)];
        __half h, l; split_h(v, h, l);
        g_bh[n * KTOT + k] = h;
        g_bl[n * KTOT + k] = l;
    }
}

// ---------------------------------------------------------------- scans
__global__ void local_scan_kernel(const float* __restrict__ u) {
    int p = threadIdx.x, c = blockIdx.x;
    float lr = g_lbr[p], li = g_lbi[p], br = g_bcr[p], bi = g_bci[p];
    float xr = 0.0f, xi = 0.0f;
    const float* up = u + (size_t)(c * CLEN) * P_DIM + p;
#pragma unroll 4
    for (int i = 0; i < CLEN; i++) {
        float uv = up[(size_t)i * P_DIM];
        float nr = fmaf(lr, xr, fmaf(-li, xi, br * uv));
        float ni = fmaf(lr, xi, fmaf( li, xr, bi * uv));
        xr = nr; xi = ni;
    }
    g_cfr[c * P_DIM + p] = xr;
    g_cfi[c * P_DIM + p] = xi;
}

__global__ void carry_kernel() {
    int p = threadIdx.x;
    double ar = g_Ar[p], ai = g_Ai[p], cr = 0.0, ci = 0.0;
    for (int c = 0; c < NCHUNK; c++) {
        g_cir[c * P_DIM + p] = (float)cr;
        g_cii[c * P_DIM + p] = (float)ci;
        double fr = (double)g_cfr[c * P_DIM + p];
        double fi = (double)g_cfi[c * P_DIM + p];
        double nr = ar * cr - ai * ci + fr;
        double ni = ar * ci + ai * cr + fi;
        cr = nr; ci = ni;
    }
}

__global__ void final_scan_kernel(const float* __restrict__ u) {
    int p = threadIdx.x, c = blockIdx.x;
    float lr = g_lbr[p], li = g_lbi[p], br = g_bcr[p], bi = g_bci[p];
    float xr = g_cir[c * P_DIM + p];
    float xi = g_cii[c * P_DIM + p];
    const float* up = u + (size_t)(c * CLEN) * P_DIM + p;
    size_t row = (size_t)(c * CLEN);
#pragma unroll 4
    for (int i = 0; i < CLEN; i++) {
        float uv = up[(size_t)i * P_DIM];
        float nr = fmaf(lr, xr, fmaf(-li, xi, br * uv));
        float ni = fmaf(lr, xi, fmaf( li, xr, bi * uv));
        xr = nr; xi = ni;
        size_t base = (row + i) * KTOT;
        __half h, l;
        split_h(xr, h, l);
        g_ah[base + p] = h;
        g_al[base + p] = l;
        split_h(xi, h, l);
        g_ah[base + P_DIM + p] = h;
        g_al[base + P_DIM + p] = l;
    }
}

// ---------------------------------------------------------------- GEMM (mma.sync f16 x3)
// C[m][n] = sum_k A[m][k] * B[n][k],  A = Ah+Al, B = Bh+Bl,
// C ~= Ah*Bh + Ah*Bl + Al*Bh, thresholded at 1.0.
#define GBM 128
#define GBN 128
#define GBK 32
#define STAGES 3
#define NK (KTOT / GBK)              // 32
#define APITCH 40                    // fp16 per smem row (32 + 8 pad)
#define PLANE_BYTES (128 * APITCH * 2)       // 10240
#define STAGE_BYTES (4 * PLANE_BYTES)        // 40960: Ah|Al|Bh|Bl
#define GSMEM_TOTAL (STAGES * STAGE_BYTES)   // 122880

__global__ __launch_bounds__(256, 1)
void gemm_spike_mma(float* __restrict__ out) {
    extern __shared__ char smem[];
    const uint32_t sbase = smem_u32(smem);
    const int tid = threadIdx.x;
    const int lane = tid & 31;
    const int wid = tid >> 5;
    const int warpM = wid & 1;           // 2 warps over M (64 rows each)
    const int warpN = wid >> 1;          // 4 warps over N (32 cols each)
    const int bm = blockIdx.y * GBM;
    const int bn = blockIdx.x * GBN;

    // ---- stage loader (cp.async) ----
    auto load_stage = [&](int s) {
        const int kbase = s * GBK;
        const uint32_t sbuf = sbase + (uint32_t)(s % STAGES) * STAGE_BYTES;
#pragma unroll
        for (int it = 0; it < 4; it++) {                 // A: 1024 chunks of 16B
            int idx = tid + it * 256;
            int plane = idx >> 9;                        // 0=h, 1=l
            int row = (idx >> 2) & 127;
            int kc = idx & 3;
            const __half* src = (plane ? g_al : g_ah) +
                                (size_t)(bm + row) * KTOT + kbase + kc * 8;
            cp16(sbuf + (uint32_t)plane * PLANE_BYTES + row * 80 + kc * 16, src);
        }
#pragma unroll
        for (int it = 0; it < 4; it++) {                 // B: 1024 chunks
            int idx = tid + it * 256;
            int plane = idx >> 9;
            int row = (idx >> 2) & 127;
            int kc = idx & 3;
            const __half* src = (plane ? g_bl : g_bh) +
                                (size_t)(bn + row) * KTOT + kbase + kc * 8;
            cp16(sbuf + 2 * PLANE_BYTES + (uint32_t)plane * PLANE_BYTES + row * 80 + kc * 16, src);
        }
    };

    float acc[4][4][4];
#pragma unroll
    for (int i = 0; i < 4; i++)
#pragma unroll
        for (int j = 0; j < 4; j++)
#pragma unroll
            for (int q = 0; q < 4; q++) acc[i][j][q] = 0.0f;

    // prologue: prefetch STAGES-1 stages
    load_stage(0);
    asm volatile("cp.async.commit_group;" ::: "memory");
    load_stage(1);
    asm volatile("cp.async.commit_group;" ::: "memory");

    // precomputed intra-warp ldmatrix offsets (element indices in the 80B-pitch tiles)
    const int a_row = warpM * 64 + (lane & 15);
    const int a_koff = (lane >> 4) << 3;
    const int b_row = warpN * 32 + (lane & 7) + ((lane >> 4) << 3);
    const int b_koff = ((lane >> 3) & 1) << 3;

    for (int k = 0; k < NK; k++) {
        asm volatile("cp.async.wait_group 1;" ::: "memory");
        __syncthreads();
        if (k + 2 < NK) load_stage(k + 2);
        asm volatile("cp.async.commit_group;" ::: "memory");

        const uint32_t sbuf = sbase + (uint32_t)(k % STAGES) * STAGE_BYTES;
        const uint32_t sAh = sbuf;
        const uint32_t sAl = sbuf + PLANE_BYTES;
        const uint32_t sBh = sbuf + 2 * PLANE_BYTES;
        const uint32_t sBl = sbuf + 3 * PLANE_BYTES;

#pragma unroll
        for (int kk = 0; kk < 2; kk++) {                 // two k16 per stage
            const int kloc = kk * 16;
            uint32_t ah[4][4], al[4][4];
#pragma unroll
            for (int mt = 0; mt < 4; mt++) {
                uint32_t off = (uint32_t)((a_row + mt * 16) * APITCH + kloc + a_koff) * 2;
                ldsm4(ah[mt], sAh + off);
                ldsm4(al[mt], sAl + off);
            }
            uint32_t bh[2][4], bl[2][4];
#pragma unroll
            for (int nh = 0; nh < 2; nh++) {
                uint32_t off = (uint32_t)((b_row + nh * 16) * APITCH + kloc + b_koff) * 2;
                ldsm4(bh[nh], sBh + off);
                ldsm4(bl[nh], sBl + off);
            }
#pragma unroll
            for (int mt = 0; mt < 4; mt++)
#pragma unroll
                for (int nt = 0; nt < 4; nt++) {
                    uint32_t* bfh = &bh[nt >> 1][(nt & 1) * 2];
                    uint32_t* bfl = &bl[nt >> 1][(nt & 1) * 2];
                    MMA16816(acc[mt][nt], ah[mt], bfh);
                    MMA16816(acc[mt][nt], ah[mt], bfl);
                    MMA16816(acc[mt][nt], al[mt], bfh);
                }
        }
    }

    // ---- epilogue: threshold + store ----
#pragma unroll
    for (int mt = 0; mt < 4; mt++) {
        int row0 = bm + warpM * 64 + mt * 16 + (lane >> 2);
#pragma unroll
        for (int nt = 0; nt < 4; nt++) {
            int col = bn + warpN * 32 + nt * 8 + (lane & 3) * 2;
            float2 v0, v1;
            v0.x = acc[mt][nt][0] > 1.0f ? 1.0f : 0.0f;
            v0.y = acc[mt][nt][1] > 1.0f ? 1.0f : 0.0f;
            v1.x = acc[mt][nt][2] > 1.0f ? 1.0f : 0.0f;
            v1.y = acc[mt][nt][3] > 1.0f ? 1.0f : 0.0f;
            *(float2*)(out + (size_t)row0 * P_DIM + col) = v0;
            *(float2*)(out + (size_t)(row0 + 8) * P_DIM + col) = v1;
        }
    }
}

// ---------------------------------------------------------------- launch
extern "C" void kernel_launch(void* const* d_in, const int* in_sizes, int n_in,
                              void* d_out, int out_size) {
    const float* u        = (const float*)d_in[0];
    const float* Lambda   = (const float*)d_in[1];
    const float* log_step = (const float*)d_in[2];
    const float* V_re     = (const float*)d_in[3];
    const float* V_im     = (const float*)d_in[4];
    float* out            = (float*)d_out;
    (void)in_sizes; (void)n_in; (void)out_size;

    cudaFuncSetAttribute(gemm_spike_mma,
                         cudaFuncAttributeMaxDynamicSharedMemorySize, GSMEM_TOTAL);

    setup_kernel<<<1, P_DIM>>>(Lambda, log_step);
    bprep_kernel<<<P_DIM, 256>>>(V_re, V_im);
    local_scan_kernel<<<NCHUNK, P_DIM>>>(u);
    carry_kernel<<<1, P_DIM>>>();
    final_scan_kernel<<<NCHUNK, P_DIM>>>(u);

    dim3 grid(P_DIM / GBN, L_DIM / GBM);   // (4, 128)
    gemm_spike_mma<<<grid, 256, GSMEM_TOTAL>>>(out);
}

// round 4
// speedup vs baseline: 2.5804x; 1.6869x over previous
#include <cuda_runtime.h>
#include <cuda_fp16.h>
#include <cstdint>

// ---------------------------------------------------------------- dims
#define L_DIM 16384
#define P_DIM 512
#define NCHUNK 256
#define CLEN (L_DIM / NCHUNK)        // 64
#define KTOT 1024                    // complex concat: [Xr | Xi]

// ---------------------------------------------------------------- scratch
__device__ float g_lbr[P_DIM], g_lbi[P_DIM];
__device__ float g_bcr[P_DIM], g_bci[P_DIM];
__device__ double g_Ar[P_DIM], g_Ai[P_DIM];
__device__ float g_cfr[NCHUNK * P_DIM], g_cfi[NCHUNK * P_DIM];
__device__ float g_cir[NCHUNK * P_DIM], g_cii[NCHUNK * P_DIM];
// A = [Xr | Xi] as fp16 Dekker split planes, row-major [L][1024]
__device__ __half g_ah[(size_t)L_DIM * KTOT];
__device__ __half g_al[(size_t)L_DIM * KTOT];
// B = [Vr | -Vi] split planes, row-major [512][1024] (row = output channel)
__device__ __half g_bh[P_DIM * KTOT];
__device__ __half g_bl[P_DIM * KTOT];

// ---------------------------------------------------------------- helpers
__device__ __forceinline__ uint32_t smem_u32(const void* p) {
    uint32_t a;
    asm("{ .reg .u64 t; cvta.to.shared.u64 t, %1; cvt.u32.u64 %0, t; }" : "=r"(a) : "l"(p));
    return a;
}
__device__ __forceinline__ void split_h(float x, __half& h, __half& l) {
    h = __float2half_rn(x);
    float r = x - __half2float(h);
    l = __float2half_rn(r);
}
__device__ __forceinline__ void cp16(uint32_t dst, const void* src) {
    asm volatile("cp.async.cg.shared.global [%0], [%1], 16;" :: "r"(dst), "l"(src));
}
__device__ __forceinline__ void ldsm4(uint32_t* r, uint32_t addr) {
    asm volatile("ldmatrix.sync.aligned.m8n8.x4.shared.b16 {%0,%1,%2,%3}, [%4];"
                 : "=r"(r[0]), "=r"(r[1]), "=r"(r[2]), "=r"(r[3]) : "r"(addr));
}
#define MMA16816(c, a, b)                                                        \
    asm volatile("mma.sync.aligned.m16n8k16.row.col.f32.f16.f16.f32 "            \
                 "{%0,%1,%2,%3}, {%4,%5,%6,%7}, {%8,%9}, {%0,%1,%2,%3};"         \
                 : "+f"((c)[0]), "+f"((c)[1]), "+f"((c)[2]), "+f"((c)[3])        \
                 : "r"((a)[0]), "r"((a)[1]), "r"((a)[2]), "r"((a)[3]),           \
                   "r"((b)[0]), "r"((b)[1]))

// ---------------------------------------------------------------- setup
__global__ void setup_kernel(const float* __restrict__ Lambda,
                             const float* __restrict__ log_step) {
    int p = blockIdx.x * blockDim.x + threadIdx.x;
    if (p >= P_DIM) return;
    float lre = -expf(Lambda[2 * p + 0]);
    float lim =  Lambda[2 * p + 1];
    float s   =  expf(log_step[p]);
    float er  =  expf(lre * s);
    float lbr = er * cosf(lim * s);
    float lbi = er * sinf(lim * s);
    g_lbr[p] = lbr; g_lbi[p] = lbi;
    float den = lre * lre + lim * lim;
    float nr = lbr - 1.0f, ni = lbi;
    g_bcr[p] = (nr * lre + ni * lim) / den;
    g_bci[p] = (ni * lre - nr * lim) / den;
    // A = lam^CLEN in double via repeated squaring of the fp32-rounded lam.
    double ar = 1.0, ai = 0.0, br = (double)lbr, bi = (double)lbi;
    int e = CLEN;
    while (e) {
        if (e & 1) { double t = ar * br - ai * bi; ai = ar * bi + ai * br; ar = t; }
        double t2 = br * br - bi * bi; bi = 2.0 * br * bi; br = t2;
        e >>= 1;
    }
    g_Ar[p] = ar; g_Ai[p] = ai;
}

// fp16 split of B = [Vr | -Vi]
__global__ void bprep_kernel(const float* __restrict__ Vr,
                             const float* __restrict__ Vi) {
    int n = blockIdx.x;
    for (int k = threadIdx.x; k < KTOT; k += blockDim.x) {
        float v = (k < P_DIM) ? Vr[n * P_DIM + k] : -Vi[n * P_DIM + (k - P_DIM)];
        __half h, l; split_h(v, h, l);
        g_bh[n * KTOT + k] = h;
        g_bl[n * KTOT + k] = l;
    }
}

// ---------------------------------------------------------------- scans
__global__ void local_scan_kernel(const float* __restrict__ u) {
    int p = threadIdx.x, c = blockIdx.x;
    float lr = g_lbr[p], li = g_lbi[p], br = g_bcr[p], bi = g_bci[p];
    float xr = 0.0f, xi = 0.0f;
    const float* up = u + (size_t)(c * CLEN) * P_DIM + p;
#pragma unroll 4
    for (int i = 0; i < CLEN; i++) {
        float uv = up[(size_t)i * P_DIM];
        float nr = fmaf(lr, xr, fmaf(-li, xi, br * uv));
        float ni = fmaf(lr, xi, fmaf( li, xr, bi * uv));
        xr = nr; xi = ni;
    }
    g_cfr[c * P_DIM + p] = xr;
    g_cfi[c * P_DIM + p] = xi;
}

// Log-depth inter-chunk carry: per channel p, inclusive Kogge-Stone scan of
// S_c = f_c + A * S_{c-1} over the NCHUNK chunk-finals; carry-in_c = S_{c-1}.
// Double precision throughout; reorder error ~1e-15 << fp32 rounding.
__global__ void carry_scan_kernel() {
    int p = blockIdx.x;        // channel
    int c = threadIdx.x;       // chunk
    __shared__ double sr[NCHUNK], si[NCHUNK];
    double vr = (double)g_cfr[c * P_DIM + p];
    double vi = (double)g_cfi[c * P_DIM + p];
    double pr = g_Ar[p], pi = g_Ai[p];       // A^(2^s), s = 0 initially
#pragma unroll
    for (int s = 1; s < NCHUNK; s <<= 1) {
        sr[c] = vr; si[c] = vi;
        __syncthreads();
        double tr = 0.0, ti = 0.0;
        if (c >= s) { tr = sr[c - s]; ti = si[c - s]; }
        __syncthreads();
        vr += pr * tr - pi * ti;
        vi += pr * ti + pi * tr;
        double npr = pr * pr - pi * pi;
        pi = 2.0 * pr * pi;
        pr = npr;
    }
    sr[c] = vr; si[c] = vi;
    __syncthreads();
    g_cir[c * P_DIM + p] = (c == 0) ? 0.0f : (float)sr[c - 1];
    g_cii[c * P_DIM + p] = (c == 0) ? 0.0f : (float)si[c - 1];
}

__global__ void final_scan_kernel(const float* __restrict__ u) {
    int p = threadIdx.x, c = blockIdx.x;
    float lr = g_lbr[p], li = g_lbi[p], br = g_bcr[p], bi = g_bci[p];
    float xr = g_cir[c * P_DIM + p];
    float xi = g_cii[c * P_DIM + p];
    const float* up = u + (size_t)(c * CLEN) * P_DIM + p;
    size_t row = (size_t)(c * CLEN);
#pragma unroll 4
    for (int i = 0; i < CLEN; i++) {
        float uv = up[(size_t)i * P_DIM];
        float nr = fmaf(lr, xr, fmaf(-li, xi, br * uv));
        float ni = fmaf(lr, xi, fmaf( li, xr, bi * uv));
        xr = nr; xi = ni;
        size_t base = (row + i) * KTOT;
        __half h, l;
        split_h(xr, h, l);
        g_ah[base + p] = h;
        g_al[base + p] = l;
        split_h(xi, h, l);
        g_ah[base + P_DIM + p] = h;
        g_al[base + P_DIM + p] = l;
    }
}

// ---------------------------------------------------------------- GEMM (mma.sync f16 x3)
// C[m][n] = sum_k A[m][k] * B[n][k],  A = Ah+Al, B = Bh+Bl,
// C ~= Ah*Bh + Ah*Bl + Al*Bh, thresholded at 1.0.
#define GBM 128
#define GBN 128
#define GBK 32
#define STAGES 3
#define NK (KTOT / GBK)              // 32
#define APITCH 40                    // fp16 per smem row (32 + 8 pad)
#define PLANE_BYTES (128 * APITCH * 2)       // 10240
#define STAGE_BYTES (4 * PLANE_BYTES)        // 40960: Ah|Al|Bh|Bl
#define GSMEM_TOTAL (STAGES * STAGE_BYTES)   // 122880

__global__ __launch_bounds__(256, 1)
void gemm_spike_mma(float* __restrict__ out) {
    extern __shared__ char smem[];
    const uint32_t sbase = smem_u32(smem);
    const int tid = threadIdx.x;
    const int lane = tid & 31;
    const int wid = tid >> 5;
    const int warpM = wid & 1;           // 2 warps over M (64 rows each)
    const int warpN = wid >> 1;          // 4 warps over N (32 cols each)
    const int bm = blockIdx.y * GBM;
    const int bn = blockIdx.x * GBN;

    // ---- stage loader (cp.async) ----
    auto load_stage = [&](int s) {
        const int kbase = s * GBK;
        const uint32_t sbuf = sbase + (uint32_t)(s % STAGES) * STAGE_BYTES;
#pragma unroll
        for (int it = 0; it < 4; it++) {                 // A: 1024 chunks of 16B
            int idx = tid + it * 256;
            int plane = idx >> 9;                        // 0=h, 1=l
            int row = (idx >> 2) & 127;
            int kc = idx & 3;
            const __half* src = (plane ? g_al : g_ah) +
                                (size_t)(bm + row) * KTOT + kbase + kc * 8;
            cp16(sbuf + (uint32_t)plane * PLANE_BYTES + row * 80 + kc * 16, src);
        }
#pragma unroll
        for (int it = 0; it < 4; it++) {                 // B: 1024 chunks
            int idx = tid + it * 256;
            int plane = idx >> 9;
            int row = (idx >> 2) & 127;
            int kc = idx & 3;
            const __half* src = (plane ? g_bl : g_bh) +
                                (size_t)(bn + row) * KTOT + kbase + kc * 8;
            cp16(sbuf + 2 * PLANE_BYTES + (uint32_t)plane * PLANE_BYTES + row * 80 + kc * 16, src);
        }
    };

    float acc[4][4][4];
#pragma unroll
    for (int i = 0; i < 4; i++)
#pragma unroll
        for (int j = 0; j < 4; j++)
#pragma unroll
            for (int q = 0; q < 4; q++) acc[i][j][q] = 0.0f;

    // prologue: prefetch STAGES-1 stages
    load_stage(0);
    asm volatile("cp.async.commit_group;" ::: "memory");
    load_stage(1);
    asm volatile("cp.async.commit_group;" ::: "memory");

    // precomputed intra-warp ldmatrix offsets (element indices, 80B pitch rows)
    const int a_row = warpM * 64 + (lane & 15);
    const int a_koff = (lane >> 4) << 3;
    const int b_row = warpN * 32 + (lane & 7) + ((lane >> 4) << 3);
    const int b_koff = ((lane >> 3) & 1) << 3;

    for (int k = 0; k < NK; k++) {
        asm volatile("cp.async.wait_group 1;" ::: "memory");
        __syncthreads();
        if (k + 2 < NK) load_stage(k + 2);
        asm volatile("cp.async.commit_group;" ::: "memory");

        const uint32_t sbuf = sbase + (uint32_t)(k % STAGES) * STAGE_BYTES;
        const uint32_t sAh = sbuf;
        const uint32_t sAl = sbuf + PLANE_BYTES;
        const uint32_t sBh = sbuf + 2 * PLANE_BYTES;
        const uint32_t sBl = sbuf + 3 * PLANE_BYTES;

#pragma unroll
        for (int kk = 0; kk < 2; kk++) {                 // two k16 per stage
            const int kloc = kk * 16;
            uint32_t ah[4][4], al[4][4];
#pragma unroll
            for (int mt = 0; mt < 4; mt++) {
                uint32_t off = (uint32_t)((a_row + mt * 16) * APITCH + kloc + a_koff) * 2;
                ldsm4(ah[mt], sAh + off);
                ldsm4(al[mt], sAl + off);
            }
            uint32_t bh[2][4], bl[2][4];
#pragma unroll
            for (int nh = 0; nh < 2; nh++) {
                uint32_t off = (uint32_t)((b_row + nh * 16) * APITCH + kloc + b_koff) * 2;
                ldsm4(bh[nh], sBh + off);
                ldsm4(bl[nh], sBl + off);
            }
#pragma unroll
            for (int mt = 0; mt < 4; mt++)
#pragma unroll
                for (int nt = 0; nt < 4; nt++) {
                    uint32_t* bfh = &bh[nt >> 1][(nt & 1) * 2];
                    uint32_t* bfl = &bl[nt >> 1][(nt & 1) * 2];
                    MMA16816(acc[mt][nt], ah[mt], bfh);
                    MMA16816(acc[mt][nt], ah[mt], bfl);
                    MMA16816(acc[mt][nt], al[mt], bfh);
                }
        }
    }

    // ---- epilogue: threshold + store ----
#pragma unroll
    for (int mt = 0; mt < 4; mt++) {
        int row0 = bm + warpM * 64 + mt * 16 + (lane >> 2);
#pragma unroll
        for (int nt = 0; nt < 4; nt++) {
            int col = bn + warpN * 32 + nt * 8 + (lane & 3) * 2;
            float2 v0, v1;
            v0.x = acc[mt][nt][0] > 1.0f ? 1.0f : 0.0f;
            v0.y = acc[mt][nt][1] > 1.0f ? 1.0f : 0.0f;
            v1.x = acc[mt][nt][2] > 1.0f ? 1.0f : 0.0f;
            v1.y = acc[mt][nt][3] > 1.0f ? 1.0f : 0.0f;
            *(float2*)(out + (size_t)row0 * P_DIM + col) = v0;
            *(float2*)(out + (size_t)(row0 + 8) * P_DIM + col) = v1;
        }
    }
}

// ---------------------------------------------------------------- launch
extern "C" void kernel_launch(void* const* d_in, const int* in_sizes, int n_in,
                              void* d_out, int out_size) {
    const float* u        = (const float*)d_in[0];
    const float* Lambda   = (const float*)d_in[1];
    const float* log_step = (const float*)d_in[2];
    const float* V_re     = (const float*)d_in[3];
    const float* V_im     = (const float*)d_in[4];
    float* out            = (float*)d_out;
    (void)in_sizes; (void)n_in; (void)out_size;

    cudaFuncSetAttribute(gemm_spike_mma,
                         cudaFuncAttributeMaxDynamicSharedMemorySize, GSMEM_TOTAL);

    setup_kernel<<<1, P_DIM>>>(Lambda, log_step);
    bprep_kernel<<<P_DIM, 256>>>(V_re, V_im);
    local_scan_kernel<<<NCHUNK, P_DIM>>>(u);
    carry_scan_kernel<<<P_DIM, NCHUNK>>>();
    final_scan_kernel<<<NCHUNK, P_DIM>>>(u);

    dim3 grid(P_DIM / GBN, L_DIM / GBM);   // (4, 128)
    gemm_spike_mma<<<grid, 256, GSMEM_TOTAL>>>(out);
}

// round 5
// speedup vs baseline: 2.6928x; 1.0436x over previous
#include <cuda_runtime.h>
#include <cuda_fp16.h>
#include <cstdint>

// ---------------------------------------------------------------- dims
#define L_DIM 16384
#define P_DIM 512
#define NCHUNK 256
#define CLEN (L_DIM / NCHUNK)        // 64
#define KTOT 1024                    // complex concat: [Xr | Xi]

// ---------------------------------------------------------------- scratch
__device__ float g_lbr[P_DIM], g_lbi[P_DIM];
__device__ float g_bcr[P_DIM], g_bci[P_DIM];
__device__ double g_Ar[P_DIM], g_Ai[P_DIM];
__device__ float g_cfr[NCHUNK * P_DIM], g_cfi[NCHUNK * P_DIM];
__device__ float g_cir[NCHUNK * P_DIM], g_cii[NCHUNK * P_DIM];
// A = [Xr | Xi] as fp16 Dekker split planes, row-major [L][1024]
__device__ __half g_ah[(size_t)L_DIM * KTOT];
__device__ __half g_al[(size_t)L_DIM * KTOT];
// B = [Vr | -Vi] split planes, row-major [512][1024] (row = output channel)
__device__ __half g_bh[P_DIM * KTOT];
__device__ __half g_bl[P_DIM * KTOT];

// ---------------------------------------------------------------- helpers
__device__ __forceinline__ uint32_t smem_u32(const void* p) {
    uint32_t a;
    asm("{ .reg .u64 t; cvta.to.shared.u64 t, %1; cvt.u32.u64 %0, t; }" : "=r"(a) : "l"(p));
    return a;
}
__device__ __forceinline__ void split_h(float x, __half& h, __half& l) {
    h = __float2half_rn(x);
    float r = x - __half2float(h);
    l = __float2half_rn(r);
}
__device__ __forceinline__ void cp16(uint32_t dst, const void* src) {
    asm volatile("cp.async.cg.shared.global [%0], [%1], 16;" :: "r"(dst), "l"(src));
}
__device__ __forceinline__ void ldsm4(uint32_t* r, uint32_t addr) {
    asm volatile("ldmatrix.sync.aligned.m8n8.x4.shared.b16 {%0,%1,%2,%3}, [%4];"
                 : "=r"(r[0]), "=r"(r[1]), "=r"(r[2]), "=r"(r[3]) : "r"(addr));
}
#define MMA16816(c, a, b)                                                        \
    asm volatile("mma.sync.aligned.m16n8k16.row.col.f32.f16.f16.f32 "            \
                 "{%0,%1,%2,%3}, {%4,%5,%6,%7}, {%8,%9}, {%0,%1,%2,%3};"         \
                 : "+f"((c)[0]), "+f"((c)[1]), "+f"((c)[2]), "+f"((c)[3])        \
                 : "r"((a)[0]), "r"((a)[1]), "r"((a)[2]), "r"((a)[3]),           \
                   "r"((b)[0]), "r"((b)[1]))

// ---------------------------------------------------------------- prep
// Fused: block n prepares B split row n (all threads) and channel-n scan
// constants (thread 0 only).
__global__ void prep_kernel(const float* __restrict__ Lambda,
                            const float* __restrict__ log_step,
                            const float* __restrict__ Vr,
                            const float* __restrict__ Vi) {
    int n = blockIdx.x;
    for (int k = threadIdx.x; k < KTOT; k += blockDim.x) {
        float v = (k < P_DIM) ? Vr[n * P_DIM + k] : -Vi[n * P_DIM + (k - P_DIM)];
        __half h, l; split_h(v, h, l);
        g_bh[n * KTOT + k] = h;
        g_bl[n * KTOT + k] = l;
    }
    if (threadIdx.x == 0) {
        int p = n;
        float lre = -expf(Lambda[2 * p + 0]);
        float lim =  Lambda[2 * p + 1];
        float s   =  expf(log_step[p]);
        float er  =  expf(lre * s);
        float lbr = er * cosf(lim * s);
        float lbi = er * sinf(lim * s);
        g_lbr[p] = lbr; g_lbi[p] = lbi;
        float den = lre * lre + lim * lim;
        float nr = lbr - 1.0f, ni = lbi;
        g_bcr[p] = (nr * lre + ni * lim) / den;
        g_bci[p] = (ni * lre - nr * lim) / den;
        // A = lam^CLEN in double via repeated squaring of the fp32-rounded lam.
        double ar = 1.0, ai = 0.0, br = (double)lbr, bi = (double)lbi;
        int e = CLEN;
        while (e) {
            if (e & 1) { double t = ar * br - ai * bi; ai = ar * bi + ai * br; ar = t; }
            double t2 = br * br - bi * bi; bi = 2.0 * br * bi; br = t2;
            e >>= 1;
        }
        g_Ar[p] = ar; g_Ai[p] = ai;
    }
}

// ---------------------------------------------------------------- scans
// grid (NCHUNK, 2), block 256: p = by*256 + tid, c = bx.
__global__ void local_scan_kernel(const float* __restrict__ u) {
    int p = blockIdx.y * 256 + threadIdx.x;
    int c = blockIdx.x;
    float lr = g_lbr[p], li = g_lbi[p], br = g_bcr[p], bi = g_bci[p];
    float xr = 0.0f, xi = 0.0f;
    const float* up = u + (size_t)(c * CLEN) * P_DIM + p;
#pragma unroll 4
    for (int i = 0; i < CLEN; i++) {
        float uv = up[(size_t)i * P_DIM];
        float nr = fmaf(lr, xr, fmaf(-li, xi, br * uv));
        float ni = fmaf(lr, xi, fmaf( li, xr, bi * uv));
        xr = nr; xi = ni;
    }
    g_cfr[c * P_DIM + p] = xr;
    g_cfi[c * P_DIM + p] = xi;
}

// Shuffle-based log-depth inter-chunk carry scan (double precision).
// Block = 256 threads = NCHUNK chunks for channel p = blockIdx.x.
// Inclusive combine: S_c = f_c + A * S_{c-1}.  Output: exclusive prefix.
__global__ void carry_scan_kernel() {
    const int p = blockIdx.x;
    const int c = threadIdx.x;
    const int lane = c & 31;
    const int w = c >> 5;                 // 8 warps

    double vr = (double)g_cfr[c * P_DIM + p];
    double vi = (double)g_cfi[c * P_DIM + p];
    double qr = g_Ar[p], qi = g_Ai[p];    // A^(2^s), s=0

    double p2r[5], p2i[5];                // A^1, A^2, A^4, A^8, A^16
    int kidx = 0;
#pragma unroll
    for (int s = 1; s < 32; s <<= 1) {
        p2r[kidx] = qr; p2i[kidx] = qi; kidx++;
        double tr = __shfl_up_sync(0xffffffffu, vr, s);
        double ti = __shfl_up_sync(0xffffffffu, vi, s);
        if (lane >= s) {
            vr = fma(qr, tr, fma(-qi, ti, vr));
            vi = fma(qr, ti, fma( qi, tr, vi));
        }
        double nqr = qr * qr - qi * qi;
        qi = 2.0 * qr * qi;
        qr = nqr;                          // now A^(2^(s+1))
    }
    // qr,qi = A^32

    __shared__ double swr[8], swi[8];
    if (lane == 31) { swr[w] = vr; swi[w] = vi; }
    __syncthreads();

    if (w == 0 && lane < 8) {              // scan 8 warp aggregates, mult A^32
        double xr = swr[lane], xi = swi[lane];
        double mr = qr, mi = qi;
#pragma unroll
        for (int s = 1; s < 8; s <<= 1) {
            double tr = __shfl_up_sync(0xffu, xr, s);
            double ti = __shfl_up_sync(0xffu, xi, s);
            if (lane >= s) {
                xr = fma(mr, tr, fma(-mi, ti, xr));
                xi = fma(mr, ti, fma( mi, tr, xi));
            }
            double nmr = mr * mr - mi * mi;
            mi = 2.0 * mr * mi;
            mr = nmr;
        }
        swr[lane] = xr; swi[lane] = xi;
    }
    __syncthreads();

    // exclusive local prefix within warp
    double er = __shfl_up_sync(0xffffffffu, vr, 1);
    double ei = __shfl_up_sync(0xffffffffu, vi, 1);
    if (lane == 0) { er = 0.0; ei = 0.0; }

    // compose with previous warps: + A^lane * Wagg[w-1]
    if (w > 0) {
        double plr = 1.0, pli = 0.0;       // A^lane from saved power-of-2 squares
#pragma unroll
        for (int k = 0; k < 5; k++) {
            if ((lane >> k) & 1) {
                double t = plr * p2r[k] - pli * p2i[k];
                pli = plr * p2i[k] + pli * p2r[k];
                plr = t;
            }
        }
        double Wr = swr[w - 1], Wi = swi[w - 1];
        er = fma(plr, Wr, fma(-pli, Wi, er));
        ei = fma(plr, Wi, fma( pli, Wr, ei));
    }

    g_cir[c * P_DIM + p] = (float)er;
    g_cii[c * P_DIM + p] = (float)ei;
}

// grid (NCHUNK, 2), block 256.
__global__ void final_scan_kernel(const float* __restrict__ u) {
    int p = blockIdx.y * 256 + threadIdx.x;
    int c = blockIdx.x;
    float lr = g_lbr[p], li = g_lbi[p], br = g_bcr[p], bi = g_bci[p];
    float xr = g_cir[c * P_DIM + p];
    float xi = g_cii[c * P_DIM + p];
    const float* up = u + (size_t)(c * CLEN) * P_DIM + p;
    size_t row = (size_t)(c * CLEN);
#pragma unroll 4
    for (int i = 0; i < CLEN; i++) {
        float uv = up[(size_t)i * P_DIM];
        float nr = fmaf(lr, xr, fmaf(-li, xi, br * uv));
        float ni = fmaf(lr, xi, fmaf( li, xr, bi * uv));
        xr = nr; xi = ni;
        size_t base = (row + i) * KTOT;
        __half h, l;
        split_h(xr, h, l);
        g_ah[base + p] = h;
        g_al[base + p] = l;
        split_h(xi, h, l);
        g_ah[base + P_DIM + p] = h;
        g_al[base + P_DIM + p] = l;
    }
}

// ---------------------------------------------------------------- GEMM (mma.sync f16 x3)
// C[m][n] = sum_k A[m][k] * B[n][k],  A = Ah+Al, B = Bh+Bl,
// C ~= Ah*Bh + Ah*Bl + Al*Bh, thresholded at 1.0.
#define GBM 128
#define GBN 128
#define GBK 32
#define STAGES 3
#define NK (KTOT / GBK)              // 32
#define APITCH 40                    // fp16 per smem row (32 + 8 pad)
#define PLANE_BYTES (128 * APITCH * 2)       // 10240
#define STAGE_BYTES (4 * PLANE_BYTES)        // 40960: Ah|Al|Bh|Bl
#define GSMEM_TOTAL (STAGES * STAGE_BYTES)   // 122880

__global__ __launch_bounds__(256, 1)
void gemm_spike_mma(float* __restrict__ out) {
    extern __shared__ char smem[];
    const uint32_t sbase = smem_u32(smem);
    const int tid = threadIdx.x;
    const int lane = tid & 31;
    const int wid = tid >> 5;
    const int warpM = wid & 1;           // 2 warps over M (64 rows each)
    const int warpN = wid >> 1;          // 4 warps over N (32 cols each)
    const int bm = blockIdx.y * GBM;
    const int bn = blockIdx.x * GBN;

    auto load_stage = [&](int s) {
        const int kbase = s * GBK;
        const uint32_t sbuf = sbase + (uint32_t)(s % STAGES) * STAGE_BYTES;
#pragma unroll
        for (int it = 0; it < 4; it++) {                 // A: 1024 chunks of 16B
            int idx = tid + it * 256;
            int plane = idx >> 9;                        // 0=h, 1=l
            int row = (idx >> 2) & 127;
            int kc = idx & 3;
            const __half* src = (plane ? g_al : g_ah) +
                                (size_t)(bm + row) * KTOT + kbase + kc * 8;
            cp16(sbuf + (uint32_t)plane * PLANE_BYTES + row * 80 + kc * 16, src);
        }
#pragma unroll
        for (int it = 0; it < 4; it++) {                 // B: 1024 chunks
            int idx = tid + it * 256;
            int plane = idx >> 9;
            int row = (idx >> 2) & 127;
            int kc = idx & 3;
            const __half* src = (plane ? g_bl : g_bh) +
                                (size_t)(bn + row) * KTOT + kbase + kc * 8;
            cp16(sbuf + 2 * PLANE_BYTES + (uint32_t)plane * PLANE_BYTES + row * 80 + kc * 16, src);
        }
    };

    float acc[4][4][4];
#pragma unroll
    for (int i = 0; i < 4; i++)
#pragma unroll
        for (int j = 0; j < 4; j++)
#pragma unroll
            for (int q = 0; q < 4; q++) acc[i][j][q] = 0.0f;

    load_stage(0);
    asm volatile("cp.async.commit_group;" ::: "memory");
    load_stage(1);
    asm volatile("cp.async.commit_group;" ::: "memory");

    const int a_row = warpM * 64 + (lane & 15);
    const int a_koff = (lane >> 4) << 3;
    const int b_row = warpN * 32 + (lane & 7) + ((lane >> 4) << 3);
    const int b_koff = ((lane >> 3) & 1) << 3;

    for (int k = 0; k < NK; k++) {
        asm volatile("cp.async.wait_group 1;" ::: "memory");
        __syncthreads();
        if (k + 2 < NK) load_stage(k + 2);
        asm volatile("cp.async.commit_group;" ::: "memory");

        const uint32_t sbuf = sbase + (uint32_t)(k % STAGES) * STAGE_BYTES;
        const uint32_t sAh = sbuf;
        const uint32_t sAl = sbuf + PLANE_BYTES;
        const uint32_t sBh = sbuf + 2 * PLANE_BYTES;
        const uint32_t sBl = sbuf + 3 * PLANE_BYTES;

#pragma unroll
        for (int kk = 0; kk < 2; kk++) {
            const int kloc = kk * 16;
            uint32_t ah[4][4], al[4][4];
#pragma unroll
            for (int mt = 0; mt < 4; mt++) {
                uint32_t off = (uint32_t)((a_row + mt * 16) * APITCH + kloc + a_koff) * 2;
                ldsm4(ah[mt], sAh + off);
                ldsm4(al[mt], sAl + off);
            }
            uint32_t bh[2][4], bl[2][4];
#pragma unroll
            for (int nh = 0; nh < 2; nh++) {
                uint32_t off = (uint32_t)((b_row + nh * 16) * APITCH + kloc + b_koff) * 2;
                ldsm4(bh[nh], sBh + off);
                ldsm4(bl[nh], sBl + off);
            }
#pragma unroll
            for (int mt = 0; mt < 4; mt++)
#pragma unroll
                for (int nt = 0; nt < 4; nt++) {
                    uint32_t* bfh = &bh[nt >> 1][(nt & 1) * 2];
                    uint32_t* bfl = &bl[nt >> 1][(nt & 1) * 2];
                    MMA16816(acc[mt][nt], ah[mt], bfh);
                    MMA16816(acc[mt][nt], ah[mt], bfl);
                    MMA16816(acc[mt][nt], al[mt], bfh);
                }
        }
    }

#pragma unroll
    for (int mt = 0; mt < 4; mt++) {
        int row0 = bm + warpM * 64 + mt * 16 + (lane >> 2);
#pragma unroll
        for (int nt = 0; nt < 4; nt++) {
            int col = bn + warpN * 32 + nt * 8 + (lane & 3) * 2;
            float2 v0, v1;
            v0.x = acc[mt][nt][0] > 1.0f ? 1.0f : 0.0f;
            v0.y = acc[mt][nt][1] > 1.0f ? 1.0f : 0.0f;
            v1.x = acc[mt][nt][2] > 1.0f ? 1.0f : 0.0f;
            v1.y = acc[mt][nt][3] > 1.0f ? 1.0f : 0.0f;
            *(float2*)(out + (size_t)row0 * P_DIM + col) = v0;
            *(float2*)(out + (size_t)(row0 + 8) * P_DIM + col) = v1;
        }
    }
}

// ---------------------------------------------------------------- launch
extern "C" void kernel_launch(void* const* d_in, const int* in_sizes, int n_in,
                              void* d_out, int out_size) {
    const float* u        = (const float*)d_in[0];
    const float* Lambda   = (const float*)d_in[1];
    const float* log_step = (const float*)d_in[2];
    const float* V_re     = (const float*)d_in[3];
    const float* V_im     = (const float*)d_in[4];
    float* out            = (float*)d_out;
    (void)in_sizes; (void)n_in; (void)out_size;

    cudaFuncSetAttribute(gemm_spike_mma,
                         cudaFuncAttributeMaxDynamicSharedMemorySize, GSMEM_TOTAL);

    prep_kernel<<<P_DIM, 256>>>(Lambda, log_step, V_re, V_im);

    dim3 sg(NCHUNK, 2);
    local_scan_kernel<<<sg, 256>>>(u);
    carry_scan_kernel<<<P_DIM, NCHUNK>>>();
    final_scan_kernel<<<sg, 256>>>(u);

    dim3 grid(P_DIM / GBN, L_DIM / GBM);   // (4, 128)
    gemm_spike_mma<<<grid, 256, GSMEM_TOTAL>>>(out);
}

// round 6
// speedup vs baseline: 2.9171x; 1.0833x over previous
#include <cuda_runtime.h>
#include <cuda_fp16.h>
#include <cstdint>

// ---------------------------------------------------------------- dims
#define L_DIM 16384
#define P_DIM 512
#define NCHUNK 256
#define CLEN (L_DIM / NCHUNK)        // 64
#define KTOT 1024                    // complex concat: [Xr | Xi]

// ---------------------------------------------------------------- scratch
__device__ float g_lbr[P_DIM], g_lbi[P_DIM];
__device__ float g_bcr[P_DIM], g_bci[P_DIM];
__device__ double g_Ar[P_DIM], g_Ai[P_DIM];
__device__ float g_cfr[NCHUNK * P_DIM], g_cfi[NCHUNK * P_DIM];
__device__ float g_cir[NCHUNK * P_DIM], g_cii[NCHUNK * P_DIM];
// A = [Xr | Xi] as fp16 Dekker split planes, row-major [L][1024]
__device__ __half g_ah[(size_t)L_DIM * KTOT];
__device__ __half g_al[(size_t)L_DIM * KTOT];
// B = [Vr | -Vi] split planes, row-major [512][1024] (row = output channel)
__device__ __half g_bh[P_DIM * KTOT];
__device__ __half g_bl[P_DIM * KTOT];

// ---------------------------------------------------------------- helpers
__device__ __forceinline__ uint32_t smem_u32(const void* p) {
    uint32_t a;
    asm("{ .reg .u64 t; cvta.to.shared.u64 t, %1; cvt.u32.u64 %0, t; }" : "=r"(a) : "l"(p));
    return a;
}
__device__ __forceinline__ void split_h(float x, __half& h, __half& l) {
    h = __float2half_rn(x);
    float r = x - __half2float(h);
    l = __float2half_rn(r);
}
__device__ __forceinline__ void cp16(uint32_t dst, const void* src) {
    asm volatile("cp.async.cg.shared.global [%0], [%1], 16;" :: "r"(dst), "l"(src));
}
__device__ __forceinline__ void ldsm4(uint32_t* r, uint32_t addr) {
    asm volatile("ldmatrix.sync.aligned.m8n8.x4.shared.b16 {%0,%1,%2,%3}, [%4];"
                 : "=r"(r[0]), "=r"(r[1]), "=r"(r[2]), "=r"(r[3]) : "r"(addr));
}
#define MMA16816(c, a, b)                                                        \
    asm volatile("mma.sync.aligned.m16n8k16.row.col.f32.f16.f16.f32 "            \
                 "{%0,%1,%2,%3}, {%4,%5,%6,%7}, {%8,%9}, {%0,%1,%2,%3};"         \
                 : "+f"((c)[0]), "+f"((c)[1]), "+f"((c)[2]), "+f"((c)[3])        \
                 : "r"((a)[0]), "r"((a)[1]), "r"((a)[2]), "r"((a)[3]),           \
                   "r"((b)[0]), "r"((b)[1]))

// ---------------------------------------------------------------- prep
__global__ void prep_kernel(const float* __restrict__ Lambda,
                            const float* __restrict__ log_step,
                            const float* __restrict__ Vr,
                            const float* __restrict__ Vi) {
    int n = blockIdx.x;
    for (int k = threadIdx.x; k < KTOT; k += blockDim.x) {
        float v = (k < P_DIM) ? Vr[n * P_DIM + k] : -Vi[n * P_DIM + (k - P_DIM)];
        __half h, l; split_h(v, h, l);
        g_bh[n * KTOT + k] = h;
        g_bl[n * KTOT + k] = l;
    }
    if (threadIdx.x == 0) {
        int p = n;
        float lre = -expf(Lambda[2 * p + 0]);
        float lim =  Lambda[2 * p + 1];
        float s   =  expf(log_step[p]);
        float er  =  expf(lre * s);
        float lbr = er * cosf(lim * s);
        float lbi = er * sinf(lim * s);
        g_lbr[p] = lbr; g_lbi[p] = lbi;
        float den = lre * lre + lim * lim;
        float nr = lbr - 1.0f, ni = lbi;
        g_bcr[p] = (nr * lre + ni * lim) / den;
        g_bci[p] = (ni * lre - nr * lim) / den;
        double ar = 1.0, ai = 0.0, br = (double)lbr, bi = (double)lbi;
        int e = CLEN;
        while (e) {
            if (e & 1) { double t = ar * br - ai * bi; ai = ar * bi + ai * br; ar = t; }
            double t2 = br * br - bi * bi; bi = 2.0 * br * bi; br = t2;
            e >>= 1;
        }
        g_Ar[p] = ar; g_Ai[p] = ai;
    }
}

// ---------------------------------------------------------------- scans
__global__ void local_scan_kernel(const float* __restrict__ u) {
    int p = blockIdx.y * 256 + threadIdx.x;
    int c = blockIdx.x;
    float lr = g_lbr[p], li = g_lbi[p], br = g_bcr[p], bi = g_bci[p];
    float xr = 0.0f, xi = 0.0f;
    const float* up = u + (size_t)(c * CLEN) * P_DIM + p;
#pragma unroll 4
    for (int i = 0; i < CLEN; i++) {
        float uv = up[(size_t)i * P_DIM];
        float nr = fmaf(lr, xr, fmaf(-li, xi, br * uv));
        float ni = fmaf(lr, xi, fmaf( li, xr, bi * uv));
        xr = nr; xi = ni;
    }
    g_cfr[c * P_DIM + p] = xr;
    g_cfi[c * P_DIM + p] = xi;
}

// Shuffle-based log-depth inter-chunk carry scan (double precision).
__global__ void carry_scan_kernel() {
    const int p = blockIdx.x;
    const int c = threadIdx.x;
    const int lane = c & 31;
    const int w = c >> 5;

    double vr = (double)g_cfr[c * P_DIM + p];
    double vi = (double)g_cfi[c * P_DIM + p];
    double qr = g_Ar[p], qi = g_Ai[p];

    double p2r[5], p2i[5];
    int kidx = 0;
#pragma unroll
    for (int s = 1; s < 32; s <<= 1) {
        p2r[kidx] = qr; p2i[kidx] = qi; kidx++;
        double tr = __shfl_up_sync(0xffffffffu, vr, s);
        double ti = __shfl_up_sync(0xffffffffu, vi, s);
        if (lane >= s) {
            vr = fma(qr, tr, fma(-qi, ti, vr));
            vi = fma(qr, ti, fma( qi, tr, vi));
        }
        double nqr = qr * qr - qi * qi;
        qi = 2.0 * qr * qi;
        qr = nqr;
    }

    __shared__ double swr[8], swi[8];
    if (lane == 31) { swr[w] = vr; swi[w] = vi; }
    __syncthreads();

    if (w == 0 && lane < 8) {
        double xr = swr[lane], xi = swi[lane];
        double mr = qr, mi = qi;
#pragma unroll
        for (int s = 1; s < 8; s <<= 1) {
            double tr = __shfl_up_sync(0xffu, xr, s);
            double ti = __shfl_up_sync(0xffu, xi, s);
            if (lane >= s) {
                xr = fma(mr, tr, fma(-mi, ti, xr));
                xi = fma(mr, ti, fma( mi, tr, xi));
            }
            double nmr = mr * mr - mi * mi;
            mi = 2.0 * mr * mi;
            mr = nmr;
        }
        swr[lane] = xr; swi[lane] = xi;
    }
    __syncthreads();

    double er = __shfl_up_sync(0xffffffffu, vr, 1);
    double ei = __shfl_up_sync(0xffffffffu, vi, 1);
    if (lane == 0) { er = 0.0; ei = 0.0; }

    if (w > 0) {
        double plr = 1.0, pli = 0.0;
#pragma unroll
        for (int k = 0; k < 5; k++) {
            if ((lane >> k) & 1) {
                double t = plr * p2r[k] - pli * p2i[k];
                pli = plr * p2i[k] + pli * p2r[k];
                plr = t;
            }
        }
        double Wr = swr[w - 1], Wi = swi[w - 1];
        er = fma(plr, Wr, fma(-pli, Wi, er));
        ei = fma(plr, Wi, fma( pli, Wr, ei));
    }

    g_cir[c * P_DIM + p] = (float)er;
    g_cii[c * P_DIM + p] = (float)ei;
}

__global__ void final_scan_kernel(const float* __restrict__ u) {
    int p = blockIdx.y * 256 + threadIdx.x;
    int c = blockIdx.x;
    float lr = g_lbr[p], li = g_lbi[p], br = g_bcr[p], bi = g_bci[p];
    float xr = g_cir[c * P_DIM + p];
    float xi = g_cii[c * P_DIM + p];
    const float* up = u + (size_t)(c * CLEN) * P_DIM + p;
    size_t row = (size_t)(c * CLEN);
#pragma unroll 4
    for (int i = 0; i < CLEN; i++) {
        float uv = up[(size_t)i * P_DIM];
        float nr = fmaf(lr, xr, fmaf(-li, xi, br * uv));
        float ni = fmaf(lr, xi, fmaf( li, xr, bi * uv));
        xr = nr; xi = ni;
        size_t base = (row + i) * KTOT;
        __half h, l;
        split_h(xr, h, l);
        g_ah[base + p] = h;
        g_al[base + p] = l;
        split_h(xi, h, l);
        g_ah[base + P_DIM + p] = h;
        g_al[base + P_DIM + p] = l;
    }
}

// ---------------------------------------------------------------- GEMM (mma.sync f16 x3)
// 256x128 CTA tile, 8 warps as 4(M) x 2(N), 64x64 per warp.
#define GBM 256
#define GBN 128
#define GBK 32
#define STAGES 3
#define NK (KTOT / GBK)                      // 32
#define APITCH 40                            // fp16 per smem row (32 + 8 pad)
#define A_PLANE (GBM * APITCH * 2)           // 20480
#define B_PLANE (GBN * APITCH * 2)           // 10240
#define STAGE_BYTES (2 * A_PLANE + 2 * B_PLANE)   // 61440: Ah|Al|Bh|Bl
#define GSMEM_TOTAL (STAGES * STAGE_BYTES)        // 184320

__global__ __launch_bounds__(256, 1)
void gemm_spike_mma(float* __restrict__ out) {
    extern __shared__ char smem[];
    const uint32_t sbase = smem_u32(smem);
    const int tid = threadIdx.x;
    const int lane = tid & 31;
    const int wid = tid >> 5;
    const int warpM = wid & 3;            // 4 warps over M (64 rows each)
    const int warpN = wid >> 2;           // 2 warps over N (64 cols each)
    const int bm = blockIdx.y * GBM;
    const int bn = blockIdx.x * GBN;

    auto load_stage = [&](int s) {
        const int kbase = s * GBK;
        const uint32_t sbuf = sbase + (uint32_t)(s % STAGES) * STAGE_BYTES;
        // A: 2048 16B chunks (256 rows x 4 kc x 2 planes)
#pragma unroll
        for (int it = 0; it < 8; it++) {
            int idx = tid + it * 256;
            int plane = idx >> 10;
            int row = (idx >> 2) & 255;
            int kc = idx & 3;
            const __half* src = (plane ? g_al : g_ah) +
                                (size_t)(bm + row) * KTOT + kbase + kc * 8;
            cp16(sbuf + (uint32_t)plane * A_PLANE + row * 80 + kc * 16, src);
        }
        // B: 1024 16B chunks (128 rows x 4 kc x 2 planes)
#pragma unroll
        for (int it = 0; it < 4; it++) {
            int idx = tid + it * 256;
            int plane = idx >> 9;
            int row = (idx >> 2) & 127;
            int kc = idx & 3;
            const __half* src = (plane ? g_bl : g_bh) +
                                (size_t)(bn + row) * KTOT + kbase + kc * 8;
            cp16(sbuf + 2 * A_PLANE + (uint32_t)plane * B_PLANE + row * 80 + kc * 16, src);
        }
    };

    float acc[4][8][4];
#pragma unroll
    for (int i = 0; i < 4; i++)
#pragma unroll
        for (int j = 0; j < 8; j++)
#pragma unroll
            for (int q = 0; q < 4; q++) acc[i][j][q] = 0.0f;

    load_stage(0);
    asm volatile("cp.async.commit_group;" ::: "memory");
    load_stage(1);
    asm volatile("cp.async.commit_group;" ::: "memory");

    const int a_row = warpM * 64 + (lane & 15);
    const int a_koff = (lane >> 4) << 3;
    const int b_row = warpN * 64 + (lane & 7) + ((lane >> 4) << 3);
    const int b_koff = ((lane >> 3) & 1) << 3;

    for (int k = 0; k < NK; k++) {
        asm volatile("cp.async.wait_group 1;" ::: "memory");
        __syncthreads();
        if (k + 2 < NK) load_stage(k + 2);
        asm volatile("cp.async.commit_group;" ::: "memory");

        const uint32_t sbuf = sbase + (uint32_t)(k % STAGES) * STAGE_BYTES;
        const uint32_t sAh = sbuf;
        const uint32_t sAl = sbuf + A_PLANE;
        const uint32_t sBh = sbuf + 2 * A_PLANE;
        const uint32_t sBl = sbuf + 2 * A_PLANE + B_PLANE;

#pragma unroll
        for (int kk = 0; kk < 2; kk++) {
            const int kloc = kk * 16;
            uint32_t ah[4][4], al[4][4];
#pragma unroll
            for (int mt = 0; mt < 4; mt++) {
                uint32_t off = (uint32_t)((a_row + mt * 16) * APITCH + kloc + a_koff) * 2;
                ldsm4(ah[mt], sAh + off);
                ldsm4(al[mt], sAl + off);
            }
            uint32_t bh[4][4], bl[4][4];
#pragma unroll
            for (int nh = 0; nh < 4; nh++) {
                uint32_t off = (uint32_t)((b_row + nh * 16) * APITCH + kloc + b_koff) * 2;
                ldsm4(bh[nh], sBh + off);
                ldsm4(bl[nh], sBl + off);
            }
#pragma unroll
            for (int mt = 0; mt < 4; mt++)
#pragma unroll
                for (int nt = 0; nt < 8; nt++) {
                    uint32_t* bfh = &bh[nt >> 1][(nt & 1) * 2];
                    uint32_t* bfl = &bl[nt >> 1][(nt & 1) * 2];
                    MMA16816(acc[mt][nt], ah[mt], bfh);
                    MMA16816(acc[mt][nt], ah[mt], bfl);
                    MMA16816(acc[mt][nt], al[mt], bfh);
                }
        }
    }

    // ---- epilogue: threshold + store ----
#pragma unroll
    for (int mt = 0; mt < 4; mt++) {
        int row0 = bm + warpM * 64 + mt * 16 + (lane >> 2);
#pragma unroll
        for (int nt = 0; nt < 8; nt++) {
            int col = bn + warpN * 64 + nt * 8 + (lane & 3) * 2;
            float2 v0, v1;
            v0.x = acc[mt][nt][0] > 1.0f ? 1.0f : 0.0f;
            v0.y = acc[mt][nt][1] > 1.0f ? 1.0f : 0.0f;
            v1.x = acc[mt][nt][2] > 1.0f ? 1.0f : 0.0f;
            v1.y = acc[mt][nt][3] > 1.0f ? 1.0f : 0.0f;
            *(float2*)(out + (size_t)row0 * P_DIM + col) = v0;
            *(float2*)(out + (size_t)(row0 + 8) * P_DIM + col) = v1;
        }
    }
}

// ---------------------------------------------------------------- launch
extern "C" void kernel_launch(void* const* d_in, const int* in_sizes, int n_in,
                              void* d_out, int out_size) {
    const float* u        = (const float*)d_in[0];
    const float* Lambda   = (const float*)d_in[1];
    const float* log_step = (const float*)d_in[2];
    const float* V_re     = (const float*)d_in[3];
    const float* V_im     = (const float*)d_in[4];
    float* out            = (float*)d_out;
    (void)in_sizes; (void)n_in; (void)out_size;

    cudaFuncSetAttribute(gemm_spike_mma,
                         cudaFuncAttributeMaxDynamicSharedMemorySize, GSMEM_TOTAL);

    prep_kernel<<<P_DIM, 256>>>(Lambda, log_step, V_re, V_im);

    dim3 sg(NCHUNK, 2);
    local_scan_kernel<<<sg, 256>>>(u);
    carry_scan_kernel<<<P_DIM, NCHUNK>>>();
    final_scan_kernel<<<sg, 256>>>(u);

    dim3 grid(P_DIM / GBN, L_DIM / GBM);   // (4, 64)
    gemm_spike_mma<<<grid, 256, GSMEM_TOTAL>>>(out);
}

// round 7
// speedup vs baseline: 3.6687x; 1.2576x over previous
#include <cuda_runtime.h>
#include <cuda_fp16.h>
#include <cstdint>

// ---------------------------------------------------------------- dims
#define L_DIM 16384
#define P_DIM 512
#define NCHUNK 256
#define CLEN (L_DIM / NCHUNK)        // 64
#define KTOT 1024                    // complex concat: [Xr | Xi]
#define NKB (KTOT / 32)              // 32 k-blocks of 32 halves (64B)

// ---------------------------------------------------------------- scratch
__device__ float g_lbr[P_DIM], g_lbi[P_DIM];
__device__ float g_bcr[P_DIM], g_bci[P_DIM];
__device__ double g_Ar[P_DIM], g_Ai[P_DIM];
__device__ float g_cfr[NCHUNK * P_DIM], g_cfi[NCHUNK * P_DIM];
__device__ float g_cir[NCHUNK * P_DIM], g_cii[NCHUNK * P_DIM];
// A = [Xr | Xi] fp16 Dekker split planes, k-block-tiled + pre-swizzled:
//   half index = (kb*L + row)*32 + (c ^ ((row>>1)&3))*8 + pos,  kb=k>>5, c=(k>>3)&3, pos=k&7
__device__ __half g_ah[(size_t)L_DIM * KTOT];
__device__ __half g_al[(size_t)L_DIM * KTOT];
// B = [Vr | -Vi] split planes, same tiling over n: (kb*512 + n)*32 + swz
__device__ __half g_bh[P_DIM * KTOT];
__device__ __half g_bl[P_DIM * KTOT];

// ---------------------------------------------------------------- helpers
__device__ __forceinline__ uint32_t smem_u32(const void* p) {
    uint32_t a;
    asm("{ .reg .u64 t; cvta.to.shared.u64 t, %1; cvt.u32.u64 %0, t; }" : "=r"(a) : "l"(p));
    return a;
}
__device__ __forceinline__ void split_h(float x, __half& h, __half& l) {
    h = __float2half_rn(x);
    float r = x - __half2float(h);
    l = __float2half_rn(r);
}
__device__ __forceinline__ void ldsm4(uint32_t* r, uint32_t addr) {
    asm volatile("ldmatrix.sync.aligned.m8n8.x4.shared.b16 {%0,%1,%2,%3}, [%4];"
                 : "=r"(r[0]), "=r"(r[1]), "=r"(r[2]), "=r"(r[3]) : "r"(addr));
}
#define MMA16816(c, a, b)                                                        \
    asm volatile("mma.sync.aligned.m16n8k16.row.col.f32.f16.f16.f32 "            \
                 "{%0,%1,%2,%3}, {%4,%5,%6,%7}, {%8,%9}, {%0,%1,%2,%3};"         \
                 : "+f"((c)[0]), "+f"((c)[1]), "+f"((c)[2]), "+f"((c)[3])        \
                 : "r"((a)[0]), "r"((a)[1]), "r"((a)[2]), "r"((a)[3]),           \
                   "r"((b)[0]), "r"((b)[1]))

#define MBAR_INIT(a, n) asm volatile("mbarrier.init.shared.b64 [%0], %1;" :: "r"(a), "r"(n) : "memory")
#define MBAR_ARRIVE(a)  asm volatile("mbarrier.arrive.shared.b64 _, [%0];" :: "r"(a) : "memory")
#define MBAR_EXPECT_TX(a, n) asm volatile("mbarrier.arrive.expect_tx.shared.b64 _, [%0], %1;" :: "r"(a), "r"(n) : "memory")
#define MBAR_WAIT(a, ph) do {                                                      \
    uint32_t _m = (a); uint32_t _p = (ph); uint32_t _d;                            \
    asm volatile("{ .reg .pred p; mbarrier.try_wait.parity.acquire.cta.shared::cta.b64 p, [%1], %2; selp.b32 %0,1,0,p; }" \
        : "=r"(_d) : "r"(_m), "r"(_p) : "memory");                                 \
    if (!_d) {                                                                     \
        asm volatile("{ .reg .pred P1; WL_%=: mbarrier.try_wait.parity.acquire.cta.shared::cta.b64 P1, [%0], %1, 0x989680;\n\t" \
            "@P1 bra.uni WD_%=; bra.uni WL_%=; WD_%=: }" :: "r"(_m), "r"(_p) : "memory"); \
    } } while (0)
#define FENCE_ASYNC() asm volatile("fence.proxy.async.shared::cta;" ::: "memory")

__device__ __forceinline__ void bulk_g2s(uint32_t smem_dst, const void* gmem_src,
                                         uint32_t bytes, uint32_t mbar) {
    asm volatile("cp.async.bulk.shared::cluster.global.mbarrier::complete_tx::bytes "
                 "[%0], [%1], %2, [%3];"
                 :: "r"(smem_dst), "l"(gmem_src), "r"(bytes), "r"(mbar) : "memory");
}

// ---------------------------------------------------------------- prep
// Block n: B split row n into tiled-swizzled layout; thread 0: channel consts.
__global__ void prep_kernel(const float* __restrict__ Lambda,
                            const float* __restrict__ log_step,
                            const float* __restrict__ Vr,
                            const float* __restrict__ Vi) {
    int n = blockIdx.x;
    int nsw = (n >> 1) & 3;
    for (int k = threadIdx.x; k < KTOT; k += blockDim.x) {
        float v = (k < P_DIM) ? Vr[n * P_DIM + k] : -Vi[n * P_DIM + (k - P_DIM)];
        __half h, l; split_h(v, h, l);
        int kb = k >> 5;
        int c = ((k >> 3) & 3) ^ nsw;
        size_t idx = ((size_t)kb * P_DIM + n) * 32 + c * 8 + (k & 7);
        g_bh[idx] = h;
        g_bl[idx] = l;
    }
    if (threadIdx.x == 0) {
        int p = n;
        float lre = -expf(Lambda[2 * p + 0]);
        float lim =  Lambda[2 * p + 1];
        float s   =  expf(log_step[p]);
        float er  =  expf(lre * s);
        float lbr = er * cosf(lim * s);
        float lbi = er * sinf(lim * s);
        g_lbr[p] = lbr; g_lbi[p] = lbi;
        float den = lre * lre + lim * lim;
        float nr = lbr - 1.0f, ni = lbi;
        g_bcr[p] = (nr * lre + ni * lim) / den;
        g_bci[p] = (ni * lre - nr * lim) / den;
        double ar = 1.0, ai = 0.0, br = (double)lbr, bi = (double)lbi;
        int e = CLEN;
        while (e) {
            if (e & 1) { double t = ar * br - ai * bi; ai = ar * bi + ai * br; ar = t; }
            double t2 = br * br - bi * bi; bi = 2.0 * br * bi; br = t2;
            e >>= 1;
        }
        g_Ar[p] = ar; g_Ai[p] = ai;
    }
}

// ---------------------------------------------------------------- scans
__global__ void local_scan_kernel(const float* __restrict__ u) {
    int p = blockIdx.y * 256 + threadIdx.x;
    int c = blockIdx.x;
    float lr = g_lbr[p], li = g_lbi[p], br = g_bcr[p], bi = g_bci[p];
    float xr = 0.0f, xi = 0.0f;
    const float* up = u + (size_t)(c * CLEN) * P_DIM + p;
#pragma unroll 4
    for (int i = 0; i < CLEN; i++) {
        float uv = up[(size_t)i * P_DIM];
        float nr = fmaf(lr, xr, fmaf(-li, xi, br * uv));
        float ni = fmaf(lr, xi, fmaf( li, xr, bi * uv));
        xr = nr; xi = ni;
    }
    g_cfr[c * P_DIM + p] = xr;
    g_cfi[c * P_DIM + p] = xi;
}

// Shuffle-based log-depth inter-chunk carry scan (double precision).
__global__ void carry_scan_kernel() {
    const int p = blockIdx.x;
    const int c = threadIdx.x;
    const int lane = c & 31;
    const int w = c >> 5;

    double vr = (double)g_cfr[c * P_DIM + p];
    double vi = (double)g_cfi[c * P_DIM + p];
    double qr = g_Ar[p], qi = g_Ai[p];

    double p2r[5], p2i[5];
    int kidx = 0;
#pragma unroll
    for (int s = 1; s < 32; s <<= 1) {
        p2r[kidx] = qr; p2i[kidx] = qi; kidx++;
        double tr = __shfl_up_sync(0xffffffffu, vr, s);
        double ti = __shfl_up_sync(0xffffffffu, vi, s);
        if (lane >= s) {
            vr = fma(qr, tr, fma(-qi, ti, vr));
            vi = fma(qr, ti, fma( qi, tr, vi));
        }
        double nqr = qr * qr - qi * qi;
        qi = 2.0 * qr * qi;
        qr = nqr;
    }

    __shared__ double swr[8], swi[8];
    if (lane == 31) { swr[w] = vr; swi[w] = vi; }
    __syncthreads();

    if (w == 0 && lane < 8) {
        double xr = swr[lane], xi = swi[lane];
        double mr = qr, mi = qi;
#pragma unroll
        for (int s = 1; s < 8; s <<= 1) {
            double tr = __shfl_up_sync(0xffu, xr, s);
            double ti = __shfl_up_sync(0xffu, xi, s);
            if (lane >= s) {
                xr = fma(mr, tr, fma(-mi, ti, xr));
                xi = fma(mr, ti, fma( mi, tr, xi));
            }
            double nmr = mr * mr - mi * mi;
            mi = 2.0 * mr * mi;
            mr = nmr;
        }
        swr[lane] = xr; swi[lane] = xi;
    }
    __syncthreads();

    double er = __shfl_up_sync(0xffffffffu, vr, 1);
    double ei = __shfl_up_sync(0xffffffffu, vi, 1);
    if (lane == 0) { er = 0.0; ei = 0.0; }

    if (w > 0) {
        double plr = 1.0, pli = 0.0;
#pragma unroll
        for (int k = 0; k < 5; k++) {
            if ((lane >> k) & 1) {
                double t = plr * p2r[k] - pli * p2i[k];
                pli = plr * p2i[k] + pli * p2r[k];
                plr = t;
            }
        }
        double Wr = swr[w - 1], Wi = swi[w - 1];
        er = fma(plr, Wr, fma(-pli, Wi, er));
        ei = fma(plr, Wi, fma( pli, Wr, ei));
    }

    g_cir[c * P_DIM + p] = (float)er;
    g_cii[c * P_DIM + p] = (float)ei;
}

// Final scan writing A planes in tiled-swizzled layout.
__global__ void final_scan_kernel(const float* __restrict__ u) {
    int p = blockIdx.y * 256 + threadIdx.x;
    int c = blockIdx.x;
    float lr = g_lbr[p], li = g_lbi[p], br = g_bcr[p], bi = g_bci[p];
    float xr = g_cir[c * P_DIM + p];
    float xi = g_cii[c * P_DIM + p];
    const float* up = u + (size_t)(c * CLEN) * P_DIM + p;
    const size_t row0 = (size_t)(c * CLEN);
    const int kbr = p >> 5;                 // Xr k-block
    const int kbi = (P_DIM >> 5) + kbr;     // Xi k-block (offset 16)
    const int coff = (p >> 3) & 3;
    const int pos = p & 7;
#pragma unroll 4
    for (int i = 0; i < CLEN; i++) {
        float uv = up[(size_t)i * P_DIM];
        float nr = fmaf(lr, xr, fmaf(-li, xi, br * uv));
        float ni = fmaf(lr, xi, fmaf( li, xr, bi * uv));
        xr = nr; xi = ni;
        size_t row = row0 + i;
        int swz = (coff ^ ((int)(row >> 1) & 3)) * 8 + pos;
        size_t idxr = ((size_t)kbr * L_DIM + row) * 32 + swz;
        size_t idxi = ((size_t)kbi * L_DIM + row) * 32 + swz;
        __half h, l;
        split_h(xr, h, l);
        g_ah[idxr] = h;
        g_al[idxr] = l;
        split_h(xi, h, l);
        g_ah[idxi] = h;
        g_al[idxi] = l;
    }
}

// ---------------------------------------------------------------- GEMM (mma.sync f16 x3, bulk-DMA pipeline)
// 256x128 CTA tile, 8 warps 4(M) x 2(N), 64x64 per warp. 4-stage mbarrier pipe.
#define GBM 256
#define GBN 128
#define NS 4
#define NSTOT NKB                         // 32 stages of k32
#define A_PL 16384                        // 256 rows * 64B
#define B_PL 8192                         // 128 rows * 64B
#define STG (2 * A_PL + 2 * B_PL)         // 49152
#define OFF_AH 0
#define OFF_AL A_PL
#define OFF_BH (2 * A_PL)
#define OFF_BL (2 * A_PL + B_PL)
#define BAR_OFF (NS * STG)                // barriers after buffers
#define GSMEM_TOTAL (NS * STG + 128)      // 196736

__global__ __launch_bounds__(256, 1)
void gemm_spike_mma(float* __restrict__ out) {
    extern __shared__ __align__(1024) char smem[];
    const uint32_t sbase = smem_u32(smem);
    const int tid = threadIdx.x;
    const int lane = tid & 31;
    const int wid = tid >> 5;
    const int warpM = wid & 3;            // 4 warps over M (64 rows each)
    const int warpN = wid >> 2;           // 2 warps over N (64 cols each)
    const int bm = blockIdx.y * GBM;
    const int bn = blockIdx.x * GBN;

    const uint32_t full0  = sbase + BAR_OFF;        // 4 x 8B
    const uint32_t empty0 = sbase + BAR_OFF + 32;   // 4 x 8B

    if (tid == 0) {
#pragma unroll
        for (int b = 0; b < NS; b++) {
            MBAR_INIT(full0 + b * 8, 1);
            MBAR_INIT(empty0 + b * 8, 256);
        }
    }
    __syncthreads();

    auto issue = [&](int si) {
        const uint32_t buf = sbase + (uint32_t)(si & (NS - 1)) * STG;
        MBAR_EXPECT_TX(full0 + (si & (NS - 1)) * 8, STG);
        const uint32_t mb = full0 + (si & (NS - 1)) * 8;
        bulk_g2s(buf + OFF_AH, g_ah + ((size_t)si * L_DIM + bm) * 32, A_PL, mb);
        bulk_g2s(buf + OFF_AL, g_al + ((size_t)si * L_DIM + bm) * 32, A_PL, mb);
        bulk_g2s(buf + OFF_BH, g_bh + ((size_t)si * P_DIM + bn) * 32, B_PL, mb);
        bulk_g2s(buf + OFF_BL, g_bl + ((size_t)si * P_DIM + bn) * 32, B_PL, mb);
    };

    // prologue: issue first NS-1 stages
    if (tid == 0) {
        for (int si = 0; si < NS - 1; si++) issue(si);
    }

    float acc[4][8][4];
#pragma unroll
    for (int i = 0; i < 4; i++)
#pragma unroll
        for (int j = 0; j < 8; j++)
#pragma unroll
            for (int q = 0; q < 4; q++) acc[i][j][q] = 0.0f;

    // ldmatrix lane geometry (rows within tile; chunk index c in 0..3 per 64B row)
    const int a_r = warpM * 64 + (lane & 15);       // + mt*16
    const int a_cbase = (lane >> 4);                // 0/1 -> k8 half
    const int b_r = warpN * 64 + (lane & 7) + ((lane >> 4) << 3);  // + nh*16
    const int b_cbase = (lane >> 3) & 1;

    for (int s = 0; s < NSTOT; s++) {
        const int b = s & (NS - 1);
        if (tid == 0) {
            int si = s + NS - 1;
            if (si < NSTOT) {
                int bb = si & (NS - 1);
                if (si >= NS) MBAR_WAIT(empty0 + bb * 8, ((si >> 2) - 1) & 1);
                issue(si);
            }
        }
        MBAR_WAIT(full0 + b * 8, (s >> 2) & 1);

        const uint32_t buf = sbase + (uint32_t)b * STG;
        const uint32_t sAh = buf + OFF_AH;
        const uint32_t sAl = buf + OFF_AL;
        const uint32_t sBh = buf + OFF_BH;
        const uint32_t sBl = buf + OFF_BL;

#pragma unroll
        for (int kk = 0; kk < 2; kk++) {             // two k16 per 64B stage
            uint32_t ah[4][4], al[4][4];
#pragma unroll
            for (int mt = 0; mt < 4; mt++) {
                int r = a_r + mt * 16;
                int c = kk * 2 + a_cbase;
                uint32_t off = (uint32_t)(r * 64 + ((c ^ ((r >> 1) & 3)) << 4));
                ldsm4(ah[mt], sAh + off);
                ldsm4(al[mt], sAl + off);
            }
            uint32_t bh[4][4], bl[4][4];
#pragma unroll
            for (int nh = 0; nh < 4; nh++) {
                int r = b_r + nh * 16;
                int c = kk * 2 + b_cbase;
                uint32_t off = (uint32_t)(r * 64 + ((c ^ ((r >> 1) & 3)) << 4));
                ldsm4(bh[nh], sBh + off);
                ldsm4(bl[nh], sBl + off);
            }
#pragma unroll
            for (int mt = 0; mt < 4; mt++)
#pragma unroll
                for (int nt = 0; nt < 8; nt++) {
                    uint32_t* bfh = &bh[nt >> 1][(nt & 1) * 2];
                    uint32_t* bfl = &bl[nt >> 1][(nt & 1) * 2];
                    MMA16816(acc[mt][nt], ah[mt], bfh);
                    MMA16816(acc[mt][nt], ah[mt], bfl);
                    MMA16816(acc[mt][nt], al[mt], bfh);
                }
        }
        FENCE_ASYNC();
        MBAR_ARRIVE(empty0 + b * 8);
    }

    // ---- epilogue: threshold + store ----
#pragma unroll
    for (int mt = 0; mt < 4; mt++) {
        int row0 = bm + warpM * 64 + mt * 16 + (lane >> 2);
#pragma unroll
        for (int nt = 0; nt < 8; nt++) {
            int col = bn + warpN * 64 + nt * 8 + (lane & 3) * 2;
            float2 v0, v1;
            v0.x = acc[mt][nt][0] > 1.0f ? 1.0f : 0.0f;
            v0.y = acc[mt][nt][1] > 1.0f ? 1.0f : 0.0f;
            v1.x = acc[mt][nt][2] > 1.0f ? 1.0f : 0.0f;
            v1.y = acc[mt][nt][3] > 1.0f ? 1.0f : 0.0f;
            *(float2*)(out + (size_t)row0 * P_DIM + col) = v0;
            *(float2*)(out + (size_t)(row0 + 8) * P_DIM + col) = v1;
        }
    }
}

// ---------------------------------------------------------------- launch
extern "C" void kernel_launch(void* const* d_in, const int* in_sizes, int n_in,
                              void* d_out, int out_size) {
    const float* u        = (const float*)d_in[0];
    const float* Lambda   = (const float*)d_in[1];
    const float* log_step = (const float*)d_in[2];
    const float* V_re     = (const float*)d_in[3];
    const float* V_im     = (const float*)d_in[4];
    float* out            = (float*)d_out;
    (void)in_sizes; (void)n_in; (void)out_size;

    cudaFuncSetAttribute(gemm_spike_mma,
                         cudaFuncAttributeMaxDynamicSharedMemorySize, GSMEM_TOTAL);

    prep_kernel<<<P_DIM, 256>>>(Lambda, log_step, V_re, V_im);

    dim3 sg(NCHUNK, 2);
    local_scan_kernel<<<sg, 256>>>(u);
    carry_scan_kernel<<<P_DIM, NCHUNK>>>();
    final_scan_kernel<<<sg, 256>>>(u);

    dim3 grid(P_DIM / GBN, L_DIM / GBM);   // (4, 64)
    gemm_spike_mma<<<grid, 256, GSMEM_TOTAL>>>(out);
}